// round 1
// baseline (speedup 1.0000x reference)
#include <cuda_runtime.h>

#define N_NODES 100000
#define N_EDGES 500000
#define F 128

// Scratch: per-node partial layer-1 activations (pre-bias, pre-relu).
__device__ float g_A[N_NODES * F];   // h @ W1u^T
__device__ float g_B[N_NODES * F];   // h @ W1v^T

// ---------------------------------------------------------------------------
// Kernel 1: precompute A[n][o] = sum_k h[n][k]*W1[o][k]
//                      B[n][o] = sum_k h[n][k]*W1[o][128+k]
// block: 256 threads, tile = 64 nodes x 128 outs. Shared (k-major):
//   hs [128][65], w1u [128][129], w1v [128][129]  (pitches make fills/reads
//   bank-conflict-free: bank = (k + col) mod 32 with lane-varying k)
// ---------------------------------------------------------------------------
__global__ __launch_bounds__(256, 1) void precompute_kernel(
    const float* __restrict__ h, const float* __restrict__ W1)
{
    extern __shared__ float smem[];
    float* hs  = smem;                  // [128][65]
    float* w1u = hs  + 128 * 65;        // [128][129]
    float* w1v = w1u + 128 * 129;       // [128][129]

    const int tid  = threadIdx.x;
    const int lane = tid & 31;
    const int warp = tid >> 5;          // 0..7
    const int nodeBase = blockIdx.x * 64;

    // fill hs (transposed): warp handles node rows warp, warp+8, ...
    for (int r = warp; r < 64; r += 8) {
        int n = nodeBase + r;
        int nn = (n < N_NODES) ? n : 0;
        const float* hrow = h + nn * F;
        #pragma unroll
        for (int j = 0; j < 4; j++) {
            int k = lane + 32 * j;
            hs[k * 65 + r] = hrow[k];
        }
    }
    // fill w1u / w1v (transposed)
    for (int o = warp; o < 128; o += 8) {
        const float* wrow = W1 + o * 256;
        #pragma unroll
        for (int j = 0; j < 8; j++) {
            int k = lane + 32 * j;
            float v = wrow[k];
            if (k < 128) w1u[k * 129 + o]         = v;
            else         w1v[(k - 128) * 129 + o] = v;
        }
    }
    __syncthreads();

    const int tx = tid & 15;   // out groups: o = tx + 16*j
    const int ty = tid >> 4;   // node groups: n = ty + 16*i (i<4 -> 0..63)

    float accA[4][8], accB[4][8];
    #pragma unroll
    for (int i = 0; i < 4; i++)
        #pragma unroll
        for (int j = 0; j < 8; j++) { accA[i][j] = 0.f; accB[i][j] = 0.f; }

    #pragma unroll 4
    for (int k = 0; k < 128; k++) {
        float hv[4];
        #pragma unroll
        for (int i = 0; i < 4; i++) hv[i] = hs[k * 65 + ty + 16 * i];
        float wu[8], wv[8];
        #pragma unroll
        for (int j = 0; j < 8; j++) {
            wu[j] = w1u[k * 129 + tx + 16 * j];
            wv[j] = w1v[k * 129 + tx + 16 * j];
        }
        #pragma unroll
        for (int i = 0; i < 4; i++)
            #pragma unroll
            for (int j = 0; j < 8; j++) {
                accA[i][j] = fmaf(hv[i], wu[j], accA[i][j]);
                accB[i][j] = fmaf(hv[i], wv[j], accB[i][j]);
            }
    }

    #pragma unroll
    for (int i = 0; i < 4; i++) {
        int n = nodeBase + ty + 16 * i;
        if (n < N_NODES) {
            #pragma unroll
            for (int j = 0; j < 8; j++) {
                int o = tx + 16 * j;
                g_A[n * F + o] = accA[i][j];
                g_B[n * F + o] = accB[i][j];
            }
        }
    }
}

// ---------------------------------------------------------------------------
// Kernel 2: per-edge. Tile = 128 edges. 256 threads.
//   x[e][k] = relu(A[src[e]][k] + B[dst[e]][k] + b1[k])   (staged k-major)
//   y[e][o] = b2[o] + sum_k W2[o][k] x[e][k]              (8x8 reg tiles)
//   out[e]  = b3 + sum_o W3[o] * relu(y[e][o])            (shfl reduce x16)
// Shared: xs [128][129], w2s [128][129]  (k-major, conflict-free)
// ---------------------------------------------------------------------------
__global__ __launch_bounds__(256, 1) void edge_kernel(
    const int* __restrict__ src, const int* __restrict__ dst,
    const float* __restrict__ b1, const float* __restrict__ W2,
    const float* __restrict__ b2, const float* __restrict__ W3,
    const float* __restrict__ b3, float* __restrict__ out)
{
    extern __shared__ float smem[];
    float* xs  = smem;                  // [128][129]
    float* w2s = xs + 128 * 129;        // [128][129]

    __shared__ int   ssrc[128];
    __shared__ int   sdst[128];
    __shared__ float b1s[128];

    const int tid  = threadIdx.x;
    const int lane = tid & 31;
    const int warp = tid >> 5;
    const int eBase = blockIdx.x * 128;

    if (tid < 128) {
        int e = eBase + tid;
        if (e >= N_EDGES) e = N_EDGES - 1;     // clamp; store is guarded later
        ssrc[tid] = src[e];
        sdst[tid] = dst[e];
        b1s[tid]  = b1[tid];
    }

    // fill w2s (transposed): warp per out-row
    for (int o = warp; o < 128; o += 8) {
        const float* wrow = W2 + o * F;
        #pragma unroll
        for (int j = 0; j < 4; j++) {
            int k = lane + 32 * j;
            w2s[k * 129 + o] = wrow[k];
        }
    }
    __syncthreads();   // ssrc/sdst/b1s ready

    // fill xs (transposed): warp per edge-row, layer-1 fused (gather + relu)
    for (int r = warp; r < 128; r += 8) {
        const float* arow = g_A + ssrc[r] * F;
        const float* brow = g_B + sdst[r] * F;
        #pragma unroll
        for (int j = 0; j < 4; j++) {
            int k = lane + 32 * j;
            xs[k * 129 + r] = fmaxf(arow[k] + brow[k] + b1s[k], 0.f);
        }
    }
    __syncthreads();

    const int tx = tid & 15;   // out groups: o = tx + 16*j
    const int ty = tid >> 4;   // edge groups: e_local = ty + 16*i

    float b2r[8], w3r[8];
    #pragma unroll
    for (int j = 0; j < 8; j++) {
        int o = tx + 16 * j;
        b2r[j] = b2[o];
        w3r[j] = W3[o];
    }

    float acc[8][8];
    #pragma unroll
    for (int i = 0; i < 8; i++)
        #pragma unroll
        for (int j = 0; j < 8; j++) acc[i][j] = b2r[j];

    #pragma unroll 4
    for (int k = 0; k < 128; k++) {
        float xv[8], wv[8];
        #pragma unroll
        for (int i = 0; i < 8; i++) xv[i] = xs[k * 129 + ty + 16 * i];
        #pragma unroll
        for (int j = 0; j < 8; j++) wv[j] = w2s[k * 129 + tx + 16 * j];
        #pragma unroll
        for (int i = 0; i < 8; i++)
            #pragma unroll
            for (int j = 0; j < 8; j++)
                acc[i][j] = fmaf(xv[i], wv[j], acc[i][j]);
    }

    // layer 3 + reduce across the 16 tx-lanes that share an edge
    const float b3v = b3[0];
    #pragma unroll
    for (int i = 0; i < 8; i++) {
        float p = 0.f;
        #pragma unroll
        for (int j = 0; j < 8; j++)
            p = fmaf(w3r[j], fmaxf(acc[i][j], 0.f), p);
        #pragma unroll
        for (int off = 8; off >= 1; off >>= 1)
            p += __shfl_down_sync(0xffffffffu, p, off, 16);
        if (tx == 0) {
            int e = eBase + ty + 16 * i;
            if (e < N_EDGES) out[e] = p + b3v;
        }
    }
}

// ---------------------------------------------------------------------------
extern "C" void kernel_launch(void* const* d_in, const int* in_sizes, int n_in,
                              void* d_out, int out_size)
{
    const float* h   = (const float*)d_in[0];
    const int*   src = (const int*)  d_in[1];
    const int*   dst = (const int*)  d_in[2];
    const float* W1  = (const float*)d_in[3];
    const float* b1  = (const float*)d_in[4];
    const float* W2  = (const float*)d_in[5];
    const float* b2  = (const float*)d_in[6];
    const float* W3  = (const float*)d_in[7];
    const float* b3  = (const float*)d_in[8];
    float* out = (float*)d_out;

    const size_t smem_pre  = (size_t)(128 * 65 + 2 * 128 * 129) * sizeof(float); // 165,376 B
    const size_t smem_edge = (size_t)(2 * 128 * 129) * sizeof(float);            // 132,096 B

    cudaFuncSetAttribute(precompute_kernel,
                         cudaFuncAttributeMaxDynamicSharedMemorySize, (int)smem_pre);
    cudaFuncSetAttribute(edge_kernel,
                         cudaFuncAttributeMaxDynamicSharedMemorySize, (int)smem_edge);

    int nodeBlocks = (N_NODES + 63) / 64;     // 1563
    int edgeBlocks = (N_EDGES + 127) / 128;   // 3907

    precompute_kernel<<<nodeBlocks, 256, smem_pre>>>(h, W1);
    edge_kernel<<<edgeBlocks, 256, smem_edge>>>(src, dst, b1, W2, b2, W3, b3, out);
}

// round 2
// speedup vs baseline: 1.0884x; 1.0884x over previous
#include <cuda_runtime.h>

#define N_NODES 100000
#define N_EDGES 500000
#define F 128

typedef unsigned long long u64;

// Per-node layer-1 partials, interleaved: g_AB[n][0:128]=h@W1u^T, [128:256]=h@W1v^T
__device__ float g_AB[(size_t)N_NODES * 256];

// ---- packed fp32x2 helpers (B300 FFMA2 path, PTX-only) ----------------------
__device__ __forceinline__ void fma2(u64& d, u64 a, u64 b) {
    asm("fma.rn.f32x2 %0, %1, %2, %0;" : "+l"(d) : "l"(a), "l"(b));
}
__device__ __forceinline__ u64 pack2(float lo, float hi) {
    u64 r; asm("mov.b64 %0, {%1, %2};" : "=l"(r) : "f"(lo), "f"(hi)); return r;
}
__device__ __forceinline__ void unpack2(u64 v, float& lo, float& hi) {
    asm("mov.b64 {%0, %1}, %2;" : "=f"(lo), "=f"(hi) : "l"(v));
}

// ---------------------------------------------------------------------------
// Precompute: g_AB[n][o'] = sum_k h[n][k] * W'[o'][k]
//   W'[o'] = W1[o'][0:128] (o'<128)  |  W1[o'-128][128:256] (o'>=128)
// 256 thr, tile 128 nodes x 256 outs, thread tile 8 nodes x 16 outs.
// Packed along outs. hs [128k][129] (odd pitch: CF fills, broadcast reads),
// ws [128k][260] (mult-4 pitch: aligned LDS.128 reads).
// ---------------------------------------------------------------------------
__global__ __launch_bounds__(256, 1) void precompute_kernel(
    const float* __restrict__ h, const float* __restrict__ W1)
{
    extern __shared__ float smem[];
    float* hs = smem;             // [128][129]
    float* ws = hs + 128 * 129;   // [128][260]

    const int tid  = threadIdx.x;
    const int lane = tid & 31;
    const int warp = tid >> 5;
    const int nodeBase = blockIdx.x * 128;

    for (int r = warp; r < 128; r += 8) {
        int n = nodeBase + r; if (n >= N_NODES) n = N_NODES - 1;
        const float* hrow = h + (size_t)n * F;
        #pragma unroll
        for (int j = 0; j < 4; j++) {
            int k = lane + 32 * j;
            hs[k * 129 + r] = hrow[k];           // stride-129 writes: CF
        }
    }
    for (int o = warp; o < 256; o += 8) {
        const float* wrow = W1 + (size_t)(o & 127) * 256 + ((o >> 7) * 128);
        #pragma unroll
        for (int j = 0; j < 4; j++) {
            int k = lane + 32 * j;
            ws[k * 260 + o] = wrow[k];
        }
    }
    __syncthreads();

    const int tx = tid & 15;          // outs  [tx*16, tx*16+16)
    const int ty = tid >> 4;          // nodes [ty*8,  ty*8+8)

    u64 acc[8][8];                    // [node][outpair]
    #pragma unroll
    for (int i = 0; i < 8; i++)
        #pragma unroll
        for (int j = 0; j < 8; j++) acc[i][j] = 0ull;

    const float* hb = hs + ty * 8;
    const float* wb = ws + tx * 16;

    #pragma unroll 2
    for (int k = 0; k < 128; k++) {
        const float* hk = hb + k * 129;
        u64 hd[8];
        #pragma unroll
        for (int i = 0; i < 8; i++) { float v = hk[i]; hd[i] = pack2(v, v); }

        const float* wk = wb + k * 260;
        ulonglong2 w01 = *reinterpret_cast<const ulonglong2*>(wk);
        ulonglong2 w23 = *reinterpret_cast<const ulonglong2*>(wk + 4);
        ulonglong2 w45 = *reinterpret_cast<const ulonglong2*>(wk + 8);
        ulonglong2 w67 = *reinterpret_cast<const ulonglong2*>(wk + 12);
        u64 wv[8] = {w01.x, w01.y, w23.x, w23.y, w45.x, w45.y, w67.x, w67.y};

        #pragma unroll
        for (int i = 0; i < 8; i++)
            #pragma unroll
            for (int j = 0; j < 8; j++)
                fma2(acc[i][j], hd[i], wv[j]);
    }

    #pragma unroll
    for (int i = 0; i < 8; i++) {
        int n = nodeBase + ty * 8 + i;
        if (n < N_NODES) {
            u64* orow = reinterpret_cast<u64*>(g_AB + (size_t)n * 256 + tx * 16);
            #pragma unroll
            for (int j = 0; j < 8; j++) orow[j] = acc[i][j];
        }
    }
}

// ---------------------------------------------------------------------------
// Edge kernel: 256 thr, tile 256 edges x 128 outs, thread tile 16 edges x 8 outs.
// Packed along edges (pairs come free from LDS.128 of xs).
//   xs  [128k][260]  x[e][k] = relu(A[src]+B[dst]+b1)   (vector reads)
//   w2s [128k][132]  W2 k-major                          (vector reads)
// ---------------------------------------------------------------------------
__global__ __launch_bounds__(256, 1) void edge_kernel(
    const int* __restrict__ src, const int* __restrict__ dst,
    const float* __restrict__ b1, const float* __restrict__ W2,
    const float* __restrict__ b2, const float* __restrict__ W3,
    const float* __restrict__ b3, float* __restrict__ out)
{
    extern __shared__ float smem[];
    float* xs  = smem;              // [128][260]
    float* w2s = xs + 128 * 260;    // [128][132]

    __shared__ int   ssrc[256];
    __shared__ int   sdst[256];
    __shared__ float b1s[128];

    const int tid  = threadIdx.x;
    const int lane = tid & 31;
    const int warp = tid >> 5;
    const int eBase = blockIdx.x * 256;

    if (tid < 128) b1s[tid] = b1[tid];
    {
        int e = eBase + tid; if (e >= N_EDGES) e = N_EDGES - 1;
        ssrc[tid] = src[e];
        sdst[tid] = dst[e];
    }

    for (int o = warp; o < 128; o += 8) {
        const float* wrow = W2 + (size_t)o * F;
        #pragma unroll
        for (int j = 0; j < 4; j++) {
            int k = lane + 32 * j;
            w2s[k * 132 + o] = wrow[k];
        }
    }
    __syncthreads();   // ssrc/sdst/b1s ready

    for (int r = warp; r < 256; r += 8) {
        const float* arow = g_AB + (size_t)ssrc[r] * 256;
        const float* brow = g_AB + (size_t)sdst[r] * 256 + 128;
        #pragma unroll
        for (int j = 0; j < 4; j++) {
            int k = lane + 32 * j;
            xs[k * 260 + r] = fmaxf(arow[k] + brow[k] + b1s[k], 0.f);
        }
    }
    __syncthreads();

    const int tx = tid & 15;          // outs  [tx*8,  tx*8+8)
    const int ty = tid >> 4;          // edges [ty*16, ty*16+16)

    float b2r[8], w3r[8];
    #pragma unroll
    for (int j = 0; j < 8; j++) {
        int o = tx * 8 + j;
        b2r[j] = b2[o];
        w3r[j] = W3[o];
    }

    u64 acc[8][8];                    // [edgepair][out], init with b2
    #pragma unroll
    for (int ep = 0; ep < 8; ep++)
        #pragma unroll
        for (int j = 0; j < 8; j++) acc[ep][j] = pack2(b2r[j], b2r[j]);

    const float* xb = xs + ty * 16;
    const float* wb = w2s + tx * 8;

    #pragma unroll 2
    for (int k = 0; k < 128; k++) {
        const float* xk = xb + k * 260;
        ulonglong2 x01 = *reinterpret_cast<const ulonglong2*>(xk);
        ulonglong2 x23 = *reinterpret_cast<const ulonglong2*>(xk + 4);
        ulonglong2 x45 = *reinterpret_cast<const ulonglong2*>(xk + 8);
        ulonglong2 x67 = *reinterpret_cast<const ulonglong2*>(xk + 12);
        u64 xv[8] = {x01.x, x01.y, x23.x, x23.y, x45.x, x45.y, x67.x, x67.y};

        const float* wk = wb + k * 132;
        float4 wA = *reinterpret_cast<const float4*>(wk);
        float4 wB = *reinterpret_cast<const float4*>(wk + 4);
        u64 wd[8];
        wd[0] = pack2(wA.x, wA.x); wd[1] = pack2(wA.y, wA.y);
        wd[2] = pack2(wA.z, wA.z); wd[3] = pack2(wA.w, wA.w);
        wd[4] = pack2(wB.x, wB.x); wd[5] = pack2(wB.y, wB.y);
        wd[6] = pack2(wB.z, wB.z); wd[7] = pack2(wB.w, wB.w);

        #pragma unroll
        for (int ep = 0; ep < 8; ep++)
            #pragma unroll
            for (int j = 0; j < 8; j++)
                fma2(acc[ep][j], xv[ep], wd[j]);
    }

    // layer 3 + reduce across the 16 tx-lanes sharing each edge
    const float b3v = b3[0];
    #pragma unroll
    for (int ep = 0; ep < 8; ep++) {
        float plo = 0.f, phi = 0.f;
        #pragma unroll
        for (int j = 0; j < 8; j++) {
            float lo, hi; unpack2(acc[ep][j], lo, hi);
            plo = fmaf(w3r[j], fmaxf(lo, 0.f), plo);
            phi = fmaf(w3r[j], fmaxf(hi, 0.f), phi);
        }
        #pragma unroll
        for (int off = 8; off >= 1; off >>= 1) {
            plo += __shfl_down_sync(0xffffffffu, plo, off, 16);
            phi += __shfl_down_sync(0xffffffffu, phi, off, 16);
        }
        if (tx == 0) {
            int e = eBase + ty * 16 + 2 * ep;
            if (e < N_EDGES)     out[e]     = plo + b3v;
            if (e + 1 < N_EDGES) out[e + 1] = phi + b3v;
        }
    }
}

// ---------------------------------------------------------------------------
extern "C" void kernel_launch(void* const* d_in, const int* in_sizes, int n_in,
                              void* d_out, int out_size)
{
    const float* h   = (const float*)d_in[0];
    const int*   src = (const int*)  d_in[1];
    const int*   dst = (const int*)  d_in[2];
    const float* W1  = (const float*)d_in[3];
    const float* b1  = (const float*)d_in[4];
    const float* W2  = (const float*)d_in[5];
    const float* b2  = (const float*)d_in[6];
    const float* W3  = (const float*)d_in[7];
    const float* b3  = (const float*)d_in[8];
    float* out = (float*)d_out;

    const size_t smem_pre  = (size_t)(128 * 129 + 128 * 260) * sizeof(float); // 199168
    const size_t smem_edge = (size_t)(128 * 260 + 128 * 132) * sizeof(float); // 200704

    cudaFuncSetAttribute(precompute_kernel,
                         cudaFuncAttributeMaxDynamicSharedMemorySize, (int)smem_pre);
    cudaFuncSetAttribute(edge_kernel,
                         cudaFuncAttributeMaxDynamicSharedMemorySize, (int)smem_edge);

    int nodeBlocks = (N_NODES + 127) / 128;   // 782
    int edgeBlocks = (N_EDGES + 255) / 256;   // 1954

    precompute_kernel<<<nodeBlocks, 256, smem_pre>>>(h, W1);
    edge_kernel<<<edgeBlocks, 256, smem_edge>>>(src, dst, b1, W2, b2, W3, b3, out);
}

// round 4
// speedup vs baseline: 1.5830x; 1.4545x over previous
#include <cuda_runtime.h>
#include <cuda_bf16.h>
#include <cstdint>

#define N_NODES 100000
#define N_EDGES 500000

// Per-node layer-1 partials: g_AB[n][0:128] = h@W1u^T, [128:256] = h@W1v^T
__device__ float g_AB[(size_t)N_NODES * 256];

// ---------------------------------------------------------------------------
// Row-swizzled bf16 tile: 256 bytes (128 bf16) per row; 16B chunks XORed by
// (row & 7) so 8 consecutive rows at the same chunk hit 8 distinct bank
// groups -> ldmatrix (8 row-addresses / phase) and STS.64 fills are CF.
// ---------------------------------------------------------------------------
#define SW(row, cb) ((uint32_t)((row) * 256 + ((cb) ^ (((row) & 7) << 4))))

__device__ __forceinline__ uint32_t smem_u32(const void* p) {
    uint32_t a;
    asm("{ .reg .u64 t; cvta.to.shared.u64 t, %1; cvt.u32.u64 %0, t; }"
        : "=r"(a) : "l"(p));
    return a;
}

__device__ __forceinline__ void ldm_x4(uint32_t* r, uint32_t addr) {
    asm volatile("ldmatrix.sync.aligned.m8n8.x4.shared.b16 {%0,%1,%2,%3}, [%4];"
                 : "=r"(r[0]), "=r"(r[1]), "=r"(r[2]), "=r"(r[3]) : "r"(addr));
}

__device__ __forceinline__ void mma_bf16(float* d, const uint32_t* a,
                                         uint32_t b0, uint32_t b1) {
    asm volatile(
        "mma.sync.aligned.m16n8k16.row.col.f32.bf16.bf16.f32 "
        "{%0,%1,%2,%3}, {%4,%5,%6,%7}, {%8,%9}, {%0,%1,%2,%3};"
        : "+f"(d[0]), "+f"(d[1]), "+f"(d[2]), "+f"(d[3])
        : "r"(a[0]), "r"(a[1]), "r"(a[2]), "r"(a[3]), "r"(b0), "r"(b1));
}

// split 4 floats into bf16 hi / lo pairs (2-term expansion)
__device__ __forceinline__ void split4(float4 v, uint2& hi, uint2& lo) {
    __nv_bfloat162 h01 = __floats2bfloat162_rn(v.x, v.y);
    __nv_bfloat162 h23 = __floats2bfloat162_rn(v.z, v.w);
    float r0 = v.x - __low2float(h01);
    float r1 = v.y - __high2float(h01);
    float r2 = v.z - __low2float(h23);
    float r3 = v.w - __high2float(h23);
    __nv_bfloat162 l01 = __floats2bfloat162_rn(r0, r1);
    __nv_bfloat162 l23 = __floats2bfloat162_rn(r2, r3);
    hi.x = *(uint32_t*)&h01; hi.y = *(uint32_t*)&h23;
    lo.x = *(uint32_t*)&l01; lo.y = *(uint32_t*)&l23;
}

// ---------------------------------------------------------------------------
// Precompute: g_AB[n][o] = sum_k h[n][k] * W'[o][k]
//   W'[o] = W1[o][0:128] (o<128) | W1[o-128][128:256] (o>=128)
// CTA: 128 nodes x 256 outs, 8 warps (4 node-groups x 2 out-groups),
// two 128-col phases; warp tile 32 nodes x 64 outs per phase.
// ---------------------------------------------------------------------------
__global__ __launch_bounds__(256, 1) void precompute_kernel(
    const float* __restrict__ h, const float* __restrict__ W1)
{
    extern __shared__ char dyn[];
    char* base = (char*)(((uintptr_t)dyn + 1023) & ~(uintptr_t)1023);
    char* XHI = base;                  // 128 rows x 256B = 32KB
    char* XLO = base + 32768;
    char* WHI = base + 65536;          // 256 rows x 256B = 64KB
    char* WLO = base + 131072;

    const int tid  = threadIdx.x;
    const int lane = tid & 31;
    const int wid  = tid >> 5;
    const int wm   = wid & 3;          // node group (32 rows)
    const int wn   = wid >> 2;         // out group (64 cols per phase)
    const int nodeBase = blockIdx.x * 128;

    const int cb = lane * 8;           // fill byte col (uint2 per lane)

    // fill x (h tile, split)
    for (int r = wid; r < 128; r += 8) {
        int n = nodeBase + r; if (n >= N_NODES) n = N_NODES - 1;
        float4 v = *(const float4*)(h + (size_t)n * 128 + 4 * lane);
        uint2 hi, lo; split4(v, hi, lo);
        uint32_t off = SW(r, cb);
        *(uint2*)(XHI + off) = hi;
        *(uint2*)(XLO + off) = lo;
    }
    // fill W' (256 rows, split)
    for (int o = wid; o < 256; o += 8) {
        const float* wrow = W1 + (size_t)(o & 127) * 256 + ((o >> 7) << 7);
        float4 v = *(const float4*)(wrow + 4 * lane);
        uint2 hi, lo; split4(v, hi, lo);
        uint32_t off = SW(o, cb);
        *(uint2*)(WHI + off) = hi;
        *(uint2*)(WLO + off) = lo;
    }
    __syncthreads();

    const uint32_t xhi = smem_u32(XHI), xlo = smem_u32(XLO);
    const uint32_t whi = smem_u32(WHI), wlo = smem_u32(WLO);
    const int ar = wm * 32 + (lane & 15);       // ldmatrix A row
    const int kh = (lane >> 4) * 16;            // k-half byte offset

    for (int ph = 0; ph < 2; ph++) {
        float d[2][8][4];
        #pragma unroll
        for (int mt = 0; mt < 2; mt++)
            #pragma unroll
            for (int nt = 0; nt < 8; nt++)
                #pragma unroll
                for (int i = 0; i < 4; i++) d[mt][nt][i] = 0.f;

        #pragma unroll
        for (int p = 0; p < 3; p++) {
            const uint32_t Ab = (p == 2) ? xlo : xhi;
            const uint32_t Bb = (p == 1) ? wlo : whi;
            #pragma unroll
            for (int ks = 0; ks < 8; ks++) {
                const int kb = ks * 32 + kh;
                uint32_t a[2][4];
                #pragma unroll
                for (int mt = 0; mt < 2; mt++)
                    ldm_x4(a[mt], Ab + SW(ar + mt * 16, kb));
                uint32_t bf[8][2];
                #pragma unroll
                for (int j = 0; j < 4; j++) {
                    uint32_t r[4];
                    int brow = ph * 128 + wn * 64 + j * 16 + (lane & 15);
                    ldm_x4(r, Bb + SW(brow, kb));
                    bf[2 * j][0] = r[0]; bf[2 * j][1] = r[2];
                    bf[2 * j + 1][0] = r[1]; bf[2 * j + 1][1] = r[3];
                }
                #pragma unroll
                for (int mt = 0; mt < 2; mt++)
                    #pragma unroll
                    for (int nt = 0; nt < 8; nt++)
                        mma_bf16(d[mt][nt], a[mt], bf[nt][0], bf[nt][1]);
            }
        }

        // store: row = l/4 (+8), cols 2*(l%4) (+1) within each 16x8 tile
        #pragma unroll
        for (int mt = 0; mt < 2; mt++) {
            #pragma unroll
            for (int rh = 0; rh < 2; rh++) {
                int n = nodeBase + wm * 32 + mt * 16 + rh * 8 + (lane >> 2);
                if (n < N_NODES) {
                    float* orow = g_AB + (size_t)n * 256 + ph * 128
                                  + wn * 64 + (lane & 3) * 2;
                    #pragma unroll
                    for (int nt = 0; nt < 8; nt++) {
                        float2 v = make_float2(d[mt][nt][rh * 2],
                                               d[mt][nt][rh * 2 + 1]);
                        *(float2*)(orow + nt * 8) = v;
                    }
                }
            }
        }
    }
}

// ---------------------------------------------------------------------------
// Edge kernel: CTA = 128 edges x 128 outs.
//   x[e][k] = relu(A[src]+B[dst]+b1) -> split bf16 tiles
//   y = x @ W2^T (3 split HMMA products), epilogue fuses b2/relu/W3/b3.
// ---------------------------------------------------------------------------
__global__ __launch_bounds__(256, 1) void edge_kernel(
    const int* __restrict__ src, const int* __restrict__ dst,
    const float* __restrict__ b1, const float* __restrict__ W2,
    const float* __restrict__ b2, const float* __restrict__ W3,
    const float* __restrict__ b3, float* __restrict__ out)
{
    extern __shared__ char dyn[];
    char* base = (char*)(((uintptr_t)dyn + 1023) & ~(uintptr_t)1023);
    char* XHI = base;                  // 32KB each
    char* XLO = base + 32768;
    char* WHI = base + 65536;
    char* WLO = base + 98304;

    __shared__ int   ssrc[128], sdst[128];
    __shared__ __align__(16) float b1s[128];
    __shared__ float b2s[128], w3s[128];
    __shared__ float part[128][2];

    const int tid  = threadIdx.x;
    const int lane = tid & 31;
    const int wid  = tid >> 5;
    const int wm   = wid & 3;          // edge group (32 rows)
    const int wn   = wid >> 2;         // out group (64 cols)
    const int eBase = blockIdx.x * 128;

    if (tid < 128) {
        int e = eBase + tid; if (e >= N_EDGES) e = N_EDGES - 1;
        ssrc[tid] = src[e];
        sdst[tid] = dst[e];
        b1s[tid]  = b1[tid];
        b2s[tid]  = b2[tid];
        w3s[tid]  = W3[tid];
    }

    const int cb = lane * 8;

    // fill W2 (split) — no dependence on ssrc, do before sync
    for (int o = wid; o < 128; o += 8) {
        float4 v = *(const float4*)(W2 + (size_t)o * 128 + 4 * lane);
        uint2 hi, lo; split4(v, hi, lo);
        uint32_t off = SW(o, cb);
        *(uint2*)(WHI + off) = hi;
        *(uint2*)(WLO + off) = lo;
    }
    __syncthreads();   // ssrc/sdst/b1s visible

    // gather + layer1 + relu + split
    const float4 bia = *(const float4*)(b1s + 4 * lane);
    for (int r = wid; r < 128; r += 8) {
        const float* arow = g_AB + (size_t)ssrc[r] * 256;
        const float* brow = g_AB + (size_t)sdst[r] * 256 + 128;
        float4 a = *(const float4*)(arow + 4 * lane);
        float4 b = *(const float4*)(brow + 4 * lane);
        float4 x;
        x.x = fmaxf(a.x + b.x + bia.x, 0.f);
        x.y = fmaxf(a.y + b.y + bia.y, 0.f);
        x.z = fmaxf(a.z + b.z + bia.z, 0.f);
        x.w = fmaxf(a.w + b.w + bia.w, 0.f);
        uint2 hi, lo; split4(x, hi, lo);
        uint32_t off = SW(r, cb);
        *(uint2*)(XHI + off) = hi;
        *(uint2*)(XLO + off) = lo;
    }
    __syncthreads();

    const uint32_t xhi = smem_u32(XHI), xlo = smem_u32(XLO);
    const uint32_t whi = smem_u32(WHI), wlo = smem_u32(WLO);
    const int ar = wm * 32 + (lane & 15);
    const int kh = (lane >> 4) * 16;

    float d[2][8][4];
    #pragma unroll
    for (int mt = 0; mt < 2; mt++)
        #pragma unroll
        for (int nt = 0; nt < 8; nt++)
            #pragma unroll
            for (int i = 0; i < 4; i++) d[mt][nt][i] = 0.f;

    #pragma unroll
    for (int p = 0; p < 3; p++) {
        const uint32_t Ab = (p == 2) ? xlo : xhi;
        const uint32_t Bb = (p == 1) ? wlo : whi;
        #pragma unroll
        for (int ks = 0; ks < 8; ks++) {
            const int kb = ks * 32 + kh;
            uint32_t a[2][4];
            #pragma unroll
            for (int mt = 0; mt < 2; mt++)
                ldm_x4(a[mt], Ab + SW(ar + mt * 16, kb));
            uint32_t bf[8][2];
            #pragma unroll
            for (int j = 0; j < 4; j++) {
                uint32_t r[4];
                int brow = wn * 64 + j * 16 + (lane & 15);
                ldm_x4(r, Bb + SW(brow, kb));
                bf[2 * j][0] = r[0]; bf[2 * j][1] = r[2];
                bf[2 * j + 1][0] = r[1]; bf[2 * j + 1][1] = r[3];
            }
            #pragma unroll
            for (int mt = 0; mt < 2; mt++)
                #pragma unroll
                for (int nt = 0; nt < 8; nt++)
                    mma_bf16(d[mt][nt], a[mt], bf[nt][0], bf[nt][1]);
        }
    }

    // epilogue: b2 + relu + dot with W3, reduce over quad (cols), then warps
    #pragma unroll
    for (int mt = 0; mt < 2; mt++) {
        #pragma unroll
        for (int rh = 0; rh < 2; rh++) {
            float p = 0.f;
            #pragma unroll
            for (int nt = 0; nt < 8; nt++) {
                int o = wn * 64 + nt * 8 + (lane & 3) * 2;
                float v0 = fmaxf(d[mt][nt][rh * 2]     + b2s[o],     0.f);
                float v1 = fmaxf(d[mt][nt][rh * 2 + 1] + b2s[o + 1], 0.f);
                p = fmaf(w3s[o], v0, p);
                p = fmaf(w3s[o + 1], v1, p);
            }
            p += __shfl_xor_sync(0xffffffffu, p, 1);
            p += __shfl_xor_sync(0xffffffffu, p, 2);
            if ((lane & 3) == 0) {
                int er = wm * 32 + mt * 16 + rh * 8 + (lane >> 2);
                part[er][wn] = p;
            }
        }
    }
    __syncthreads();

    if (tid < 128) {
        int e = eBase + tid;
        if (e < N_EDGES) out[e] = part[tid][0] + part[tid][1] + b3[0];
    }
}

// ---------------------------------------------------------------------------
extern "C" void kernel_launch(void* const* d_in, const int* in_sizes, int n_in,
                              void* d_out, int out_size)
{
    const float* h   = (const float*)d_in[0];
    const int*   src = (const int*)  d_in[1];
    const int*   dst = (const int*)  d_in[2];
    const float* W1  = (const float*)d_in[3];
    const float* b1  = (const float*)d_in[4];
    const float* W2  = (const float*)d_in[5];
    const float* b2  = (const float*)d_in[6];
    const float* W3  = (const float*)d_in[7];
    const float* b3  = (const float*)d_in[8];
    float* out = (float*)d_out;

    const int smem_pre  = 196608 + 1024;   // x(64K) + W'(128K) + align pad
    const int smem_edge = 131072 + 1024;   // x(64K) + W2(64K) + align pad

    cudaFuncSetAttribute(precompute_kernel,
                         cudaFuncAttributeMaxDynamicSharedMemorySize, smem_pre);
    cudaFuncSetAttribute(edge_kernel,
                         cudaFuncAttributeMaxDynamicSharedMemorySize, smem_edge);

    int nodeBlocks = (N_NODES + 127) / 128;   // 782
    int edgeBlocks = (N_EDGES + 127) / 128;   // 3907

    precompute_kernel<<<nodeBlocks, 256, smem_pre>>>(h, W1);
    edge_kernel<<<edgeBlocks, 256, smem_edge>>>(src, dst, b1, W2, b2, W3, b3, out);
}

// round 5
// speedup vs baseline: 1.8687x; 1.1805x over previous
#include <cuda_runtime.h>
#include <cuda_bf16.h>
#include <cstdint>

#define N_NODES 100000
#define N_EDGES 500000

// Per-node layer-1 partials: g_AB[n][0:128] = h@W1u^T, [128:256] = h@W1v^T
__device__ float g_AB[(size_t)N_NODES * 256];

// Row-swizzled bf16 tile: 256B (128 bf16) per row; 16B chunks XORed by (row&7)
// -> ldmatrix reads and STS.64 fills are bank-conflict-free, no padding.
#define SW(row, cb) ((uint32_t)((row) * 256 + ((cb) ^ (((row) & 7) << 4))))

__device__ __forceinline__ uint32_t smem_u32(const void* p) {
    uint32_t a;
    asm("{ .reg .u64 t; cvta.to.shared.u64 t, %1; cvt.u32.u64 %0, t; }"
        : "=r"(a) : "l"(p));
    return a;
}
__device__ __forceinline__ void ldm_x4(uint32_t* r, uint32_t addr) {
    asm volatile("ldmatrix.sync.aligned.m8n8.x4.shared.b16 {%0,%1,%2,%3}, [%4];"
                 : "=r"(r[0]), "=r"(r[1]), "=r"(r[2]), "=r"(r[3]) : "r"(addr));
}
__device__ __forceinline__ void mma_bf16(float* d, const uint32_t* a,
                                         uint32_t b0, uint32_t b1) {
    asm volatile(
        "mma.sync.aligned.m16n8k16.row.col.f32.bf16.bf16.f32 "
        "{%0,%1,%2,%3}, {%4,%5,%6,%7}, {%8,%9}, {%0,%1,%2,%3};"
        : "+f"(d[0]), "+f"(d[1]), "+f"(d[2]), "+f"(d[3])
        : "r"(a[0]), "r"(a[1]), "r"(a[2]), "r"(a[3]), "r"(b0), "r"(b1));
}
__device__ __forceinline__ void split4(float4 v, uint2& hi, uint2& lo) {
    __nv_bfloat162 h01 = __floats2bfloat162_rn(v.x, v.y);
    __nv_bfloat162 h23 = __floats2bfloat162_rn(v.z, v.w);
    float r0 = v.x - __low2float(h01);
    float r1 = v.y - __high2float(h01);
    float r2 = v.z - __low2float(h23);
    float r3 = v.w - __high2float(h23);
    __nv_bfloat162 l01 = __floats2bfloat162_rn(r0, r1);
    __nv_bfloat162 l23 = __floats2bfloat162_rn(r2, r3);
    hi.x = *(uint32_t*)&h01; hi.y = *(uint32_t*)&h23;
    lo.x = *(uint32_t*)&l01; lo.y = *(uint32_t*)&l23;
}

// ---------------------------------------------------------------------------
// MMA core: X[64 rows] x W[128 rows]^T, 3 split products, warp tile 32x32.
// wm = wid&1 (row group), wn = wid>>1 (col group). d[2][4][4] accumulators.
// ---------------------------------------------------------------------------
struct Frag { float d[2][4][4]; };

__device__ __forceinline__ void mma_tile(Frag& f, uint32_t xhi, uint32_t xlo,
                                         uint32_t whi, uint32_t wlo,
                                         int wm, int wn, int lane) {
    #pragma unroll
    for (int mt = 0; mt < 2; mt++)
        #pragma unroll
        for (int nt = 0; nt < 4; nt++)
            #pragma unroll
            for (int i = 0; i < 4; i++) f.d[mt][nt][i] = 0.f;

    const int ar = wm * 32 + (lane & 15);
    const int kh = (lane >> 4) * 16;

    #pragma unroll
    for (int p = 0; p < 3; p++) {
        const uint32_t Ab = (p == 2) ? xlo : xhi;
        const uint32_t Bb = (p == 1) ? wlo : whi;
        #pragma unroll
        for (int ks = 0; ks < 8; ks++) {
            const int kb = ks * 32 + kh;
            uint32_t a[2][4];
            #pragma unroll
            for (int mt = 0; mt < 2; mt++)
                ldm_x4(a[mt], Ab + SW(ar + mt * 16, kb));
            uint32_t bf[4][2];
            #pragma unroll
            for (int j = 0; j < 2; j++) {
                uint32_t r[4];
                int brow = wn * 32 + j * 16 + (lane & 15);
                ldm_x4(r, Bb + SW(brow, kb));
                bf[2 * j][0] = r[0];     bf[2 * j][1] = r[2];
                bf[2 * j + 1][0] = r[1]; bf[2 * j + 1][1] = r[3];
            }
            #pragma unroll
            for (int mt = 0; mt < 2; mt++)
                #pragma unroll
                for (int nt = 0; nt < 4; nt++)
                    mma_bf16(f.d[mt][nt], a[mt], bf[nt][0], bf[nt][1]);
        }
    }
}

// ---------------------------------------------------------------------------
// Precompute: tile 64 nodes x 128 outs. blockIdx.x even/odd selects out-half.
// ---------------------------------------------------------------------------
__global__ __launch_bounds__(256, 2) void precompute_kernel(
    const float* __restrict__ h, const float* __restrict__ W1)
{
    extern __shared__ char dyn[];
    char* base = (char*)(((uintptr_t)dyn + 1023) & ~(uintptr_t)1023);
    char* XHI = base;                  // 64 x 256B = 16KB
    char* XLO = base + 16384;
    char* WHI = base + 32768;          // 128 x 256B = 32KB
    char* WLO = base + 65536;

    const int tid  = threadIdx.x;
    const int lane = tid & 31;
    const int wid  = tid >> 5;
    const int wm   = wid & 1;
    const int wn   = wid >> 1;
    const int nodeBase = (blockIdx.x >> 1) * 64;
    const int ob       = (blockIdx.x & 1) * 128;

    const int cb = lane * 8;

    for (int r = wid; r < 64; r += 8) {
        int n = nodeBase + r; if (n >= N_NODES) n = N_NODES - 1;
        float4 v = *(const float4*)(h + (size_t)n * 128 + 4 * lane);
        uint2 hi, lo; split4(v, hi, lo);
        uint32_t off = SW(r, cb);
        *(uint2*)(XHI + off) = hi;
        *(uint2*)(XLO + off) = lo;
    }
    for (int o = wid; o < 128; o += 8) {
        int go = ob + o;
        const float* wrow = W1 + (size_t)(go & 127) * 256 + ((go >> 7) << 7);
        float4 v = *(const float4*)(wrow + 4 * lane);
        uint2 hi, lo; split4(v, hi, lo);
        uint32_t off = SW(o, cb);
        *(uint2*)(WHI + off) = hi;
        *(uint2*)(WLO + off) = lo;
    }
    __syncthreads();

    Frag f;
    mma_tile(f, smem_u32(XHI), smem_u32(XLO), smem_u32(WHI), smem_u32(WLO),
             wm, wn, lane);

    #pragma unroll
    for (int mt = 0; mt < 2; mt++) {
        #pragma unroll
        for (int rh = 0; rh < 2; rh++) {
            int n = nodeBase + wm * 32 + mt * 16 + rh * 8 + (lane >> 2);
            if (n < N_NODES) {
                float* orow = g_AB + (size_t)n * 256 + ob
                              + wn * 32 + (lane & 3) * 2;
                #pragma unroll
                for (int nt = 0; nt < 4; nt++) {
                    float2 v = make_float2(f.d[mt][nt][rh * 2],
                                           f.d[mt][nt][rh * 2 + 1]);
                    *(float2*)(orow + nt * 8) = v;
                }
            }
        }
    }
}

// ---------------------------------------------------------------------------
// Edge kernel: tile 64 edges x 128 outs.
// ---------------------------------------------------------------------------
__global__ __launch_bounds__(256, 2) void edge_kernel(
    const int* __restrict__ src, const int* __restrict__ dst,
    const float* __restrict__ b1, const float* __restrict__ W2,
    const float* __restrict__ b2, const float* __restrict__ W3,
    const float* __restrict__ b3, float* __restrict__ out)
{
    extern __shared__ char dyn[];
    char* base = (char*)(((uintptr_t)dyn + 1023) & ~(uintptr_t)1023);
    char* XHI = base;                  // 16KB
    char* XLO = base + 16384;
    char* WHI = base + 32768;          // 32KB
    char* WLO = base + 65536;

    __shared__ float part[64][4];

    const int tid  = threadIdx.x;
    const int lane = tid & 31;
    const int wid  = tid >> 5;
    const int wm   = wid & 1;
    const int wn   = wid >> 1;
    const int eBase = blockIdx.x * 64;

    const int cb = lane * 8;

    // Phase 0: start the index-load chains early (uniform LDG -> broadcast)
    int sidx[8], didx[8];
    #pragma unroll
    for (int i = 0; i < 8; i++) {
        int e = eBase + wid + 8 * i; if (e >= N_EDGES) e = N_EDGES - 1;
        sidx[i] = __ldg(&src[e]);
        didx[i] = __ldg(&dst[e]);
    }
    float4 bia = *(const float4*)(b1 + 4 * lane);

    // Phase 1: W2 fill (independent of indices; overlaps LDG latency above)
    for (int o = wid; o < 128; o += 8) {
        float4 v = *(const float4*)(W2 + (size_t)o * 128 + 4 * lane);
        uint2 hi, lo; split4(v, hi, lo);
        uint32_t off = SW(o, cb);
        *(uint2*)(WHI + off) = hi;
        *(uint2*)(WLO + off) = lo;
    }

    // Phase 2: gather + layer1 + relu + split
    #pragma unroll
    for (int i = 0; i < 8; i++) {
        int r = wid + 8 * i;
        const float* arow = g_AB + (size_t)sidx[i] * 256;
        const float* brow = g_AB + (size_t)didx[i] * 256 + 128;
        float4 a = *(const float4*)(arow + 4 * lane);
        float4 b = *(const float4*)(brow + 4 * lane);
        float4 x;
        x.x = fmaxf(a.x + b.x + bia.x, 0.f);
        x.y = fmaxf(a.y + b.y + bia.y, 0.f);
        x.z = fmaxf(a.z + b.z + bia.z, 0.f);
        x.w = fmaxf(a.w + b.w + bia.w, 0.f);
        uint2 hi, lo; split4(x, hi, lo);
        uint32_t off = SW(r, cb);
        *(uint2*)(XHI + off) = hi;
        *(uint2*)(XLO + off) = lo;
    }
    __syncthreads();

    Frag f;
    mma_tile(f, smem_u32(XHI), smem_u32(XLO), smem_u32(WHI), smem_u32(WLO),
             wm, wn, lane);

    // Epilogue: b2 + relu + dot W3; reduce over quad, stash per out-group
    const int o0 = wn * 32 + (lane & 3) * 2;
    #pragma unroll
    for (int mt = 0; mt < 2; mt++) {
        #pragma unroll
        for (int rh = 0; rh < 2; rh++) {
            float p = 0.f;
            #pragma unroll
            for (int nt = 0; nt < 4; nt++) {
                int o = o0 + nt * 8;
                float v0 = fmaxf(f.d[mt][nt][rh * 2]     + __ldg(&b2[o]),     0.f);
                float v1 = fmaxf(f.d[mt][nt][rh * 2 + 1] + __ldg(&b2[o + 1]), 0.f);
                p = fmaf(__ldg(&W3[o]), v0, p);
                p = fmaf(__ldg(&W3[o + 1]), v1, p);
            }
            p += __shfl_xor_sync(0xffffffffu, p, 1);
            p += __shfl_xor_sync(0xffffffffu, p, 2);
            if ((lane & 3) == 0) {
                int er = wm * 32 + mt * 16 + rh * 8 + (lane >> 2);
                part[er][wn] = p;
            }
        }
    }
    __syncthreads();

    if (tid < 64) {
        int e = eBase + tid;
        if (e < N_EDGES)
            out[e] = part[tid][0] + part[tid][1] + part[tid][2] + part[tid][3]
                     + __ldg(&b3[0]);
    }
}

// ---------------------------------------------------------------------------
extern "C" void kernel_launch(void* const* d_in, const int* in_sizes, int n_in,
                              void* d_out, int out_size)
{
    const float* h   = (const float*)d_in[0];
    const int*   src = (const int*)  d_in[1];
    const int*   dst = (const int*)  d_in[2];
    const float* W1  = (const float*)d_in[3];
    const float* b1  = (const float*)d_in[4];
    const float* W2  = (const float*)d_in[5];
    const float* b2  = (const float*)d_in[6];
    const float* W3  = (const float*)d_in[7];
    const float* b3  = (const float*)d_in[8];
    float* out = (float*)d_out;

    const int smem_sz = 98304 + 1024;   // X(32K) + W(64K) + align pad

    cudaFuncSetAttribute(precompute_kernel,
                         cudaFuncAttributeMaxDynamicSharedMemorySize, smem_sz);
    cudaFuncSetAttribute(edge_kernel,
                         cudaFuncAttributeMaxDynamicSharedMemorySize, smem_sz);

    int nodeBlocks = ((N_NODES + 63) / 64) * 2;   // 3126 (x2 out-halves)
    int edgeBlocks = (N_EDGES + 63) / 64;         // 7813

    precompute_kernel<<<nodeBlocks, 256, smem_sz>>>(h, W1);
    edge_kernel<<<edgeBlocks, 256, smem_sz>>>(src, dst, b1, W2, b2, W3, b3, out);
}

// round 6
// speedup vs baseline: 4.1865x; 2.2403x over previous
#include <cuda_runtime.h>
#include <cuda_bf16.h>
#include <cstdint>

#define N_NODES 100000
#define N_EDGES 500000

// Per-node layer-1 partials: g_AB[n][0:128] = h@W1u^T, [128:256] = h@W1v^T
__device__ float g_AB[(size_t)N_NODES * 256];

// B-operand fragment tables (mma.sync m16n8k16 B-fragment order, split bf16).
// w2: [p(hi/lo)][wn(4)][ks(8)][lane(32)][reg(8)]          = 16384 u32 (64KB)
// w1: [p][ob(2)][wn(4)][ks(8)][lane(32)][reg(8)]          = 32768 u32 (128KB)
__device__ uint32_t g_w2frag[16384];
__device__ uint32_t g_w1frag[32768];

// Row-swizzled bf16 tile: 256B (128 bf16) per row; 16B chunks XORed by (row&7)
#define SW(row, cb) ((uint32_t)((row) * 256 + ((cb) ^ (((row) & 7) << 4))))

__device__ __forceinline__ uint32_t smem_u32(const void* p) {
    uint32_t a;
    asm("{ .reg .u64 t; cvta.to.shared.u64 t, %1; cvt.u32.u64 %0, t; }"
        : "=r"(a) : "l"(p));
    return a;
}
__device__ __forceinline__ void ldm_x4(uint32_t* r, uint32_t addr) {
    asm volatile("ldmatrix.sync.aligned.m8n8.x4.shared.b16 {%0,%1,%2,%3}, [%4];"
                 : "=r"(r[0]), "=r"(r[1]), "=r"(r[2]), "=r"(r[3]) : "r"(addr));
}
__device__ __forceinline__ void mma_bf16(float* d, const uint32_t* a,
                                         uint32_t b0, uint32_t b1) {
    asm volatile(
        "mma.sync.aligned.m16n8k16.row.col.f32.bf16.bf16.f32 "
        "{%0,%1,%2,%3}, {%4,%5,%6,%7}, {%8,%9}, {%0,%1,%2,%3};"
        : "+f"(d[0]), "+f"(d[1]), "+f"(d[2]), "+f"(d[3])
        : "r"(a[0]), "r"(a[1]), "r"(a[2]), "r"(a[3]), "r"(b0), "r"(b1));
}
__device__ __forceinline__ void split4(float4 v, uint2& hi, uint2& lo) {
    __nv_bfloat162 h01 = __floats2bfloat162_rn(v.x, v.y);
    __nv_bfloat162 h23 = __floats2bfloat162_rn(v.z, v.w);
    float r0 = v.x - __low2float(h01);
    float r1 = v.y - __high2float(h01);
    float r2 = v.z - __low2float(h23);
    float r3 = v.w - __high2float(h23);
    __nv_bfloat162 l01 = __floats2bfloat162_rn(r0, r1);
    __nv_bfloat162 l23 = __floats2bfloat162_rn(r2, r3);
    hi.x = *(uint32_t*)&h01; hi.y = *(uint32_t*)&h23;
    lo.x = *(uint32_t*)&l01; lo.y = *(uint32_t*)&l23;
}
__device__ __forceinline__ uint32_t split_pick(float v0, float v1, int p) {
    __nv_bfloat16 h0 = __float2bfloat16_rn(v0);
    __nv_bfloat16 h1 = __float2bfloat16_rn(v1);
    if (p) {
        h0 = __float2bfloat16_rn(v0 - __bfloat162float(h0));
        h1 = __float2bfloat16_rn(v1 - __bfloat162float(h1));
    }
    uint16_t a = *(uint16_t*)&h0, b = *(uint16_t*)&h1;
    return (uint32_t)a | ((uint32_t)b << 16);
}

// ---------------------------------------------------------------------------
// Build B-fragment tables. Fragment semantics (m16n8k16.row.col B):
//   reg r (0..7): nt = r>>1 (n block of 8), q = r&1 (k half)
//   n = wn*32 + nt*8 + (lane>>2);  k = ks*16 + q*8 + (lane&3)*2  (+1 in hi bits)
// ---------------------------------------------------------------------------
__global__ void prep_frag_kernel(const float* __restrict__ W1,
                                 const float* __restrict__ W2)
{
    int idx = blockIdx.x * 256 + threadIdx.x;
    if (idx < 16384) {
        int r = idx & 7, lane = (idx >> 3) & 31, ks = (idx >> 8) & 7;
        int wn = (idx >> 11) & 3, p = (idx >> 13) & 1;
        int n = wn * 32 + (r >> 1) * 8 + (lane >> 2);
        int k = ks * 16 + (r & 1) * 8 + (lane & 3) * 2;
        const float* row = W2 + (size_t)n * 128;
        g_w2frag[idx] = split_pick(row[k], row[k + 1], p);
    } else if (idx < 16384 + 32768) {
        int j = idx - 16384;
        int r = j & 7, lane = (j >> 3) & 31, ks = (j >> 8) & 7;
        int wn = (j >> 11) & 3, ob = (j >> 13) & 1, p = (j >> 14) & 1;
        int go = ob * 128 + wn * 32 + (r >> 1) * 8 + (lane >> 2);
        int k = ks * 16 + (r & 1) * 8 + (lane & 3) * 2;
        const float* row = W1 + (size_t)(go & 127) * 256 + ((go >> 7) << 7);
        g_w1frag[j] = split_pick(row[k], row[k + 1], p);
    }
}

// ---------------------------------------------------------------------------
// Shared MMA core: D[64 x 128] += 3 split products. A from swizzled smem
// (ldmatrix), B fragments from global tables (LDG.128, L1-resident).
// ---------------------------------------------------------------------------
__device__ __forceinline__ void mma_core(float d[2][4][4],
                                         uint32_t xhi, uint32_t xlo,
                                         const uint4* wh, const uint4* wl,
                                         int wm, int lane)
{
    const int ar = wm * 32 + (lane & 15);
    const int kh = (lane >> 4) * 16;

    #pragma unroll
    for (int ks = 0; ks < 8; ks++) {
        const int kb = ks * 32 + kh;
        uint32_t ah[2][4], al[2][4];
        ldm_x4(ah[0], xhi + SW(ar, kb));
        ldm_x4(ah[1], xhi + SW(ar + 16, kb));
        ldm_x4(al[0], xlo + SW(ar, kb));
        ldm_x4(al[1], xlo + SW(ar + 16, kb));

        uint4 h0 = __ldg(wh + ks * 64), h1 = __ldg(wh + ks * 64 + 1);
        uint4 l0 = __ldg(wl + ks * 64), l1 = __ldg(wl + ks * 64 + 1);
        uint32_t bh[4][2] = {{h0.x, h0.y}, {h0.z, h0.w}, {h1.x, h1.y}, {h1.z, h1.w}};
        uint32_t bl[4][2] = {{l0.x, l0.y}, {l0.z, l0.w}, {l1.x, l1.y}, {l1.z, l1.w}};

        #pragma unroll
        for (int mt = 0; mt < 2; mt++)
            #pragma unroll
            for (int nt = 0; nt < 4; nt++)
                mma_bf16(d[mt][nt], ah[mt], bh[nt][0], bh[nt][1]);
        #pragma unroll
        for (int mt = 0; mt < 2; mt++)
            #pragma unroll
            for (int nt = 0; nt < 4; nt++)
                mma_bf16(d[mt][nt], ah[mt], bl[nt][0], bl[nt][1]);
        #pragma unroll
        for (int mt = 0; mt < 2; mt++)
            #pragma unroll
            for (int nt = 0; nt < 4; nt++)
                mma_bf16(d[mt][nt], al[mt], bh[nt][0], bh[nt][1]);
    }
}

// ---------------------------------------------------------------------------
// Precompute: tile 64 nodes x 128 outs; blockIdx parity selects out-half.
// ---------------------------------------------------------------------------
__global__ __launch_bounds__(256, 3) void precompute_kernel(
    const float* __restrict__ h)
{
    extern __shared__ char dyn[];
    char* base = (char*)(((uintptr_t)dyn + 1023) & ~(uintptr_t)1023);
    char* XHI = base;                  // 64 x 256B = 16KB
    char* XLO = base + 16384;

    const int tid  = threadIdx.x;
    const int lane = tid & 31;
    const int wid  = tid >> 5;
    const int wm   = wid & 1;
    const int wn   = wid >> 1;
    const int nodeBase = (blockIdx.x >> 1) * 64;
    const int ob       = (blockIdx.x & 1);

    const int cb = lane * 8;

    #pragma unroll
    for (int i = 0; i < 8; i++) {
        int r = wid * 8 + i;
        int n = nodeBase + r; if (n >= N_NODES) n = N_NODES - 1;
        float4 v = *(const float4*)(h + (size_t)n * 128 + 4 * lane);
        uint2 hi, lo; split4(v, hi, lo);
        uint32_t off = SW(r, cb);
        *(uint2*)(XHI + off) = hi;
        *(uint2*)(XLO + off) = lo;
    }
    __syncthreads();

    const uint4* wh = (const uint4*)(g_w1frag + ob * 8192 + wn * 2048) + lane * 2;
    const uint4* wl = (const uint4*)(g_w1frag + 16384 + ob * 8192 + wn * 2048) + lane * 2;

    float d[2][4][4];
    #pragma unroll
    for (int mt = 0; mt < 2; mt++)
        #pragma unroll
        for (int nt = 0; nt < 4; nt++)
            #pragma unroll
            for (int i = 0; i < 4; i++) d[mt][nt][i] = 0.f;

    mma_core(d, smem_u32(XHI), smem_u32(XLO), wh, wl, wm, lane);

    #pragma unroll
    for (int mt = 0; mt < 2; mt++) {
        #pragma unroll
        for (int rh = 0; rh < 2; rh++) {
            int n = nodeBase + wm * 32 + mt * 16 + rh * 8 + (lane >> 2);
            if (n < N_NODES) {
                float* orow = g_AB + (size_t)n * 256 + ob * 128
                              + wn * 32 + (lane & 3) * 2;
                #pragma unroll
                for (int nt = 0; nt < 4; nt++) {
                    float2 v = make_float2(d[mt][nt][rh * 2],
                                           d[mt][nt][rh * 2 + 1]);
                    *(float2*)(orow + nt * 8) = v;
                }
            }
        }
    }
}

// ---------------------------------------------------------------------------
// Edge kernel: tile 64 edges x 128 outs.
// ---------------------------------------------------------------------------
__global__ __launch_bounds__(256, 3) void edge_kernel(
    const int* __restrict__ src, const int* __restrict__ dst,
    const float* __restrict__ b1, const float* __restrict__ b2,
    const float* __restrict__ W3, const float* __restrict__ b3,
    float* __restrict__ out)
{
    extern __shared__ char dyn[];
    char* base = (char*)(((uintptr_t)dyn + 1023) & ~(uintptr_t)1023);
    char* XHI = base;                  // 16KB
    char* XLO = base + 16384;

    __shared__ float part[64][4];

    const int tid  = threadIdx.x;
    const int lane = tid & 31;
    const int wid  = tid >> 5;
    const int wm   = wid & 1;
    const int wn   = wid >> 1;
    const int eBase = blockIdx.x * 64;

    const int cb = lane * 8;

    // indices early (uniform broadcast LDG), then dependent gathers
    int sidx[8], didx[8];
    #pragma unroll
    for (int i = 0; i < 8; i++) {
        int e = eBase + wid * 8 + i; if (e >= N_EDGES) e = N_EDGES - 1;
        sidx[i] = __ldg(&src[e]);
        didx[i] = __ldg(&dst[e]);
    }
    float4 bia = *(const float4*)(b1 + 4 * lane);

    #pragma unroll
    for (int i = 0; i < 8; i++) {
        int r = wid * 8 + i;
        const float* arow = g_AB + (size_t)sidx[i] * 256;
        const float* brow = g_AB + (size_t)didx[i] * 256 + 128;
        float4 a = *(const float4*)(arow + 4 * lane);
        float4 b = *(const float4*)(brow + 4 * lane);
        float4 x;
        x.x = fmaxf(a.x + b.x + bia.x, 0.f);
        x.y = fmaxf(a.y + b.y + bia.y, 0.f);
        x.z = fmaxf(a.z + b.z + bia.z, 0.f);
        x.w = fmaxf(a.w + b.w + bia.w, 0.f);
        uint2 hi, lo; split4(x, hi, lo);
        uint32_t off = SW(r, cb);
        *(uint2*)(XHI + off) = hi;
        *(uint2*)(XLO + off) = lo;
    }
    __syncthreads();

    const uint4* wh = (const uint4*)(g_w2frag + wn * 2048) + lane * 2;
    const uint4* wl = (const uint4*)(g_w2frag + 8192 + wn * 2048) + lane * 2;

    float d[2][4][4];
    #pragma unroll
    for (int mt = 0; mt < 2; mt++)
        #pragma unroll
        for (int nt = 0; nt < 4; nt++)
            #pragma unroll
            for (int i = 0; i < 4; i++) d[mt][nt][i] = 0.f;

    mma_core(d, smem_u32(XHI), smem_u32(XLO), wh, wl, wm, lane);

    // epilogue: b2 + relu + dot W3; quad reduce; combine out-groups
    const int o0 = wn * 32 + (lane & 3) * 2;
    #pragma unroll
    for (int mt = 0; mt < 2; mt++) {
        #pragma unroll
        for (int rh = 0; rh < 2; rh++) {
            float p = 0.f;
            #pragma unroll
            for (int nt = 0; nt < 4; nt++) {
                int o = o0 + nt * 8;
                float v0 = fmaxf(d[mt][nt][rh * 2]     + __ldg(&b2[o]),     0.f);
                float v1 = fmaxf(d[mt][nt][rh * 2 + 1] + __ldg(&b2[o + 1]), 0.f);
                p = fmaf(__ldg(&W3[o]), v0, p);
                p = fmaf(__ldg(&W3[o + 1]), v1, p);
            }
            p += __shfl_xor_sync(0xffffffffu, p, 1);
            p += __shfl_xor_sync(0xffffffffu, p, 2);
            if ((lane & 3) == 0) {
                int er = wm * 32 + mt * 16 + rh * 8 + (lane >> 2);
                part[er][wn] = p;
            }
        }
    }
    __syncthreads();

    if (tid < 64) {
        int e = eBase + tid;
        if (e < N_EDGES)
            out[e] = part[tid][0] + part[tid][1] + part[tid][2] + part[tid][3]
                     + __ldg(&b3[0]);
    }
}

// ---------------------------------------------------------------------------
extern "C" void kernel_launch(void* const* d_in, const int* in_sizes, int n_in,
                              void* d_out, int out_size)
{
    const float* h   = (const float*)d_in[0];
    const int*   src = (const int*)  d_in[1];
    const int*   dst = (const int*)  d_in[2];
    const float* W1  = (const float*)d_in[3];
    const float* b1  = (const float*)d_in[4];
    const float* W2  = (const float*)d_in[5];
    const float* b2  = (const float*)d_in[6];
    const float* W3  = (const float*)d_in[7];
    const float* b3  = (const float*)d_in[8];
    float* out = (float*)d_out;

    const int smem_sz = 32768 + 1024;

    cudaFuncSetAttribute(precompute_kernel,
                         cudaFuncAttributeMaxDynamicSharedMemorySize, smem_sz);
    cudaFuncSetAttribute(edge_kernel,
                         cudaFuncAttributeMaxDynamicSharedMemorySize, smem_sz);

    int prepBlocks = (16384 + 32768 + 255) / 256;   // 192
    int nodeBlocks = ((N_NODES + 63) / 64) * 2;     // 3126
    int edgeBlocks = (N_EDGES + 63) / 64;           // 7813

    prep_frag_kernel<<<prepBlocks, 256>>>(W1, W2);
    precompute_kernel<<<nodeBlocks, 256, smem_sz>>>(h);
    edge_kernel<<<edgeBlocks, 256, smem_sz>>>(src, dst, b1, b2, W3, b3, out);
}

// round 8
// speedup vs baseline: 4.4081x; 1.0529x over previous
#include <cuda_runtime.h>
#include <cuda_bf16.h>
#include <cstdint>

#define N_NODES 100000
#define N_EDGES 500000

// Per-node layer-1 partials (bias folded): g_AB[n][0:128] = h@W1u^T + b1/2,
//                                          g_AB[n][128:256] = h@W1v^T + b1/2
__device__ float g_AB[(size_t)N_NODES * 256];

// B-operand fragment tables (mma.sync m16n8k16 B-fragment order, split bf16).
__device__ uint32_t g_w2frag[16384];   // [p][wn(4)][ks(8)][lane(32)][reg(8)]
__device__ uint32_t g_w1frag[32768];   // [p][ob(2)][wn(4)][ks(8)][lane(32)][reg(8)]

// Row-swizzled bf16 tile: 256B (128 bf16) per row; 16B chunks XORed by (row&7)
#define SW(row, cb) ((uint32_t)((row) * 256 + ((cb) ^ (((row) & 7) << 4))))

__device__ __forceinline__ uint32_t smem_u32(const void* p) {
    uint32_t a;
    asm("{ .reg .u64 t; cvta.to.shared.u64 t, %1; cvt.u32.u64 %0, t; }"
        : "=r"(a) : "l"(p));
    return a;
}
__device__ __forceinline__ void ldm_x4(uint32_t* r, uint32_t addr) {
    asm volatile("ldmatrix.sync.aligned.m8n8.x4.shared.b16 {%0,%1,%2,%3}, [%4];"
                 : "=r"(r[0]), "=r"(r[1]), "=r"(r[2]), "=r"(r[3]) : "r"(addr));
}
__device__ __forceinline__ void mma_bf16(float* d, const uint32_t* a,
                                         uint32_t b0, uint32_t b1) {
    asm volatile(
        "mma.sync.aligned.m16n8k16.row.col.f32.bf16.bf16.f32 "
        "{%0,%1,%2,%3}, {%4,%5,%6,%7}, {%8,%9}, {%0,%1,%2,%3};"
        : "+f"(d[0]), "+f"(d[1]), "+f"(d[2]), "+f"(d[3])
        : "r"(a[0]), "r"(a[1]), "r"(a[2]), "r"(a[3]), "r"(b0), "r"(b1));
}
__device__ __forceinline__ void split4(float4 v, uint2& hi, uint2& lo) {
    __nv_bfloat162 h01 = __floats2bfloat162_rn(v.x, v.y);
    __nv_bfloat162 h23 = __floats2bfloat162_rn(v.z, v.w);
    float r0 = v.x - __low2float(h01);
    float r1 = v.y - __high2float(h01);
    float r2 = v.z - __low2float(h23);
    float r3 = v.w - __high2float(h23);
    __nv_bfloat162 l01 = __floats2bfloat162_rn(r0, r1);
    __nv_bfloat162 l23 = __floats2bfloat162_rn(r2, r3);
    hi.x = *(uint32_t*)&h01; hi.y = *(uint32_t*)&h23;
    lo.x = *(uint32_t*)&l01; lo.y = *(uint32_t*)&l23;
}
__device__ __forceinline__ uint32_t split_pick(float v0, float v1, int p) {
    __nv_bfloat16 h0 = __float2bfloat16_rn(v0);
    __nv_bfloat16 h1 = __float2bfloat16_rn(v1);
    if (p) {
        h0 = __float2bfloat16_rn(v0 - __bfloat162float(h0));
        h1 = __float2bfloat16_rn(v1 - __bfloat162float(h1));
    }
    uint16_t a = *(uint16_t*)&h0, b = *(uint16_t*)&h1;
    return (uint32_t)a | ((uint32_t)b << 16);
}

// ---------------------------------------------------------------------------
__global__ void prep_frag_kernel(const float* __restrict__ W1,
                                 const float* __restrict__ W2)
{
    int idx = blockIdx.x * 256 + threadIdx.x;
    if (idx < 16384) {
        int r = idx & 7, lane = (idx >> 3) & 31, ks = (idx >> 8) & 7;
        int wn = (idx >> 11) & 3, p = (idx >> 13) & 1;
        int n = wn * 32 + (r >> 1) * 8 + (lane >> 2);
        int k = ks * 16 + (r & 1) * 8 + (lane & 3) * 2;
        const float* row = W2 + (size_t)n * 128;
        g_w2frag[idx] = split_pick(row[k], row[k + 1], p);
    } else if (idx < 16384 + 32768) {
        int j = idx - 16384;
        int r = j & 7, lane = (j >> 3) & 31, ks = (j >> 8) & 7;
        int wn = (j >> 11) & 3, ob = (j >> 13) & 1, p = (j >> 14) & 1;
        int go = ob * 128 + wn * 32 + (r >> 1) * 8 + (lane >> 2);
        int k = ks * 16 + (r & 1) * 8 + (lane & 3) * 2;
        const float* row = W1 + (size_t)(go & 127) * 256 + ((go >> 7) << 7);
        g_w1frag[j] = split_pick(row[k], row[k + 1], p);
    }
}

// ---------------------------------------------------------------------------
// MMA core: D[32 x 128-slice] += 3 split products. A from swizzled smem,
// B fragments from global tables (L1-resident LDG.128).
// ---------------------------------------------------------------------------
__device__ __forceinline__ void mma_core(float d[2][4][4],
                                         uint32_t xhi, uint32_t xlo,
                                         const uint4* wh, const uint4* wl,
                                         int wm, int lane)
{
    const int ar = wm * 32 + (lane & 15);
    const int kh = (lane >> 4) * 16;

    #pragma unroll
    for (int ks = 0; ks < 8; ks++) {
        const int kb = ks * 32 + kh;
        uint32_t ah[2][4], al[2][4];
        ldm_x4(ah[0], xhi + SW(ar, kb));
        ldm_x4(ah[1], xhi + SW(ar + 16, kb));
        ldm_x4(al[0], xlo + SW(ar, kb));
        ldm_x4(al[1], xlo + SW(ar + 16, kb));

        uint4 h0 = __ldg(wh + ks * 64), h1 = __ldg(wh + ks * 64 + 1);
        uint4 l0 = __ldg(wl + ks * 64), l1 = __ldg(wl + ks * 64 + 1);
        uint32_t bh[4][2] = {{h0.x, h0.y}, {h0.z, h0.w}, {h1.x, h1.y}, {h1.z, h1.w}};
        uint32_t bl[4][2] = {{l0.x, l0.y}, {l0.z, l0.w}, {l1.x, l1.y}, {l1.z, l1.w}};

        #pragma unroll
        for (int mt = 0; mt < 2; mt++)
            #pragma unroll
            for (int nt = 0; nt < 4; nt++)
                mma_bf16(d[mt][nt], ah[mt], bh[nt][0], bh[nt][1]);
        #pragma unroll
        for (int mt = 0; mt < 2; mt++)
            #pragma unroll
            for (int nt = 0; nt < 4; nt++)
                mma_bf16(d[mt][nt], ah[mt], bl[nt][0], bl[nt][1]);
        #pragma unroll
        for (int mt = 0; mt < 2; mt++)
            #pragma unroll
            for (int nt = 0; nt < 4; nt++)
                mma_bf16(d[mt][nt], al[mt], bh[nt][0], bh[nt][1]);
    }
}

// ---------------------------------------------------------------------------
// Precompute: tile 64 nodes x 128 outs; blockIdx parity = out-half.
// Warp groups: wm = wid>>2 owns rows [wm*32, wm*32+32) for fill AND consume.
// ---------------------------------------------------------------------------
__global__ __launch_bounds__(256, 3) void precompute_kernel(
    const float* __restrict__ h, const float* __restrict__ b1)
{
    extern __shared__ char dyn[];
    char* base = (char*)(((uintptr_t)dyn + 1023) & ~(uintptr_t)1023);
    char* XHI = base;                  // 16KB
    char* XLO = base + 16384;

    const int tid  = threadIdx.x;
    const int lane = tid & 31;
    const int wid  = tid >> 5;
    const int wm   = wid >> 2;         // row group
    const int wn   = wid & 3;          // col group (also fill sub-index)
    const int nodeBase = (blockIdx.x >> 1) * 64;
    const int ob       = (blockIdx.x & 1);

    const int cb = lane * 8;
    const int fillBase = wm * 32 + wn * 8;

    #pragma unroll
    for (int i = 0; i < 8; i += 2) {
        int r0 = fillBase + i, r1 = fillBase + i + 1;
        int n0 = nodeBase + r0; if (n0 >= N_NODES) n0 = N_NODES - 1;
        int n1 = nodeBase + r1; if (n1 >= N_NODES) n1 = N_NODES - 1;
        float4 v0 = *(const float4*)(h + (size_t)n0 * 128 + 4 * lane);
        float4 v1 = *(const float4*)(h + (size_t)n1 * 128 + 4 * lane);
        uint2 hi0, lo0, hi1, lo1;
        split4(v0, hi0, lo0); split4(v1, hi1, lo1);
        uint32_t o0 = SW(r0, cb), o1 = SW(r1, cb);
        *(uint2*)(XHI + o0) = hi0; *(uint2*)(XLO + o0) = lo0;
        *(uint2*)(XHI + o1) = hi1; *(uint2*)(XLO + o1) = lo1;
    }
    // half-CTA sync: group 0 = tid<128, group 1 = tid>=128 (contiguous)
    asm volatile("bar.sync %0, 128;" :: "r"(wm + 1) : "memory");

    const uint4* wh = (const uint4*)(g_w1frag + ob * 8192 + wn * 2048) + lane * 2;
    const uint4* wl = (const uint4*)(g_w1frag + 16384 + ob * 8192 + wn * 2048) + lane * 2;

    float d[2][4][4];
    #pragma unroll
    for (int mt = 0; mt < 2; mt++)
        #pragma unroll
        for (int nt = 0; nt < 4; nt++)
            #pragma unroll
            for (int i = 0; i < 4; i++) d[mt][nt][i] = 0.f;

    mma_core(d, smem_u32(XHI), smem_u32(XLO), wh, wl, wm, lane);

    // epilogue: add b1/2 per nt column block (FIX: bias indexed per nt)
    const int bcol0 = wn * 32 + (lane & 3) * 2;   // column within the 128-half
    float hb[4][2];
    #pragma unroll
    for (int nt = 0; nt < 4; nt++) {
        hb[nt][0] = 0.5f * __ldg(&b1[bcol0 + nt * 8]);
        hb[nt][1] = 0.5f * __ldg(&b1[bcol0 + nt * 8 + 1]);
    }
    const int oc = ob * 128 + bcol0;
    #pragma unroll
    for (int mt = 0; mt < 2; mt++) {
        #pragma unroll
        for (int rh = 0; rh < 2; rh++) {
            int n = nodeBase + wm * 32 + mt * 16 + rh * 8 + (lane >> 2);
            if (n < N_NODES) {
                float* orow = g_AB + (size_t)n * 256 + oc;
                #pragma unroll
                for (int nt = 0; nt < 4; nt++) {
                    float2 v = make_float2(d[mt][nt][rh * 2]     + hb[nt][0],
                                           d[mt][nt][rh * 2 + 1] + hb[nt][1]);
                    *(float2*)(orow + nt * 8) = v;
                }
            }
        }
    }
}

// ---------------------------------------------------------------------------
// Edge kernel: tile 64 edges x 128 outs; bias already folded into g_AB.
// ---------------------------------------------------------------------------
__global__ __launch_bounds__(256, 3) void edge_kernel(
    const int* __restrict__ src, const int* __restrict__ dst,
    const float* __restrict__ b2, const float* __restrict__ W3,
    const float* __restrict__ b3, float* __restrict__ out)
{
    extern __shared__ char dyn[];
    char* base = (char*)(((uintptr_t)dyn + 1023) & ~(uintptr_t)1023);
    char* XHI = base;                  // 16KB
    char* XLO = base + 16384;

    __shared__ float part[64][4];

    const int tid  = threadIdx.x;
    const int lane = tid & 31;
    const int wid  = tid >> 5;
    const int wm   = wid >> 2;
    const int wn   = wid & 3;
    const int eBase = blockIdx.x * 64;

    const int cb = lane * 8;
    const int fillBase = wm * 32 + wn * 8;

    // indices for this warp's 8 fill rows (uniform broadcast LDG)
    int sidx[8], didx[8];
    #pragma unroll
    for (int i = 0; i < 8; i++) {
        int e = eBase + fillBase + i; if (e >= N_EDGES) e = N_EDGES - 1;
        sidx[i] = __ldg(&src[e]);
        didx[i] = __ldg(&dst[e]);
    }

    // gather + layer1(+folded bias) + relu + split, 2 rows per step (4 LDGs)
    #pragma unroll
    for (int i = 0; i < 8; i += 2) {
        int r0 = fillBase + i, r1 = fillBase + i + 1;
        const float* a0p = g_AB + (size_t)sidx[i] * 256;
        const float* b0p = g_AB + (size_t)didx[i] * 256 + 128;
        const float* a1p = g_AB + (size_t)sidx[i + 1] * 256;
        const float* b1p = g_AB + (size_t)didx[i + 1] * 256 + 128;
        float4 a0 = *(const float4*)(a0p + 4 * lane);
        float4 b0 = *(const float4*)(b0p + 4 * lane);
        float4 a1 = *(const float4*)(a1p + 4 * lane);
        float4 b1v = *(const float4*)(b1p + 4 * lane);
        float4 x0, x1;
        x0.x = fmaxf(a0.x + b0.x, 0.f); x0.y = fmaxf(a0.y + b0.y, 0.f);
        x0.z = fmaxf(a0.z + b0.z, 0.f); x0.w = fmaxf(a0.w + b0.w, 0.f);
        x1.x = fmaxf(a1.x + b1v.x, 0.f); x1.y = fmaxf(a1.y + b1v.y, 0.f);
        x1.z = fmaxf(a1.z + b1v.z, 0.f); x1.w = fmaxf(a1.w + b1v.w, 0.f);
        uint2 hi0, lo0, hi1, lo1;
        split4(x0, hi0, lo0); split4(x1, hi1, lo1);
        uint32_t o0 = SW(r0, cb), o1 = SW(r1, cb);
        *(uint2*)(XHI + o0) = hi0; *(uint2*)(XLO + o0) = lo0;
        *(uint2*)(XHI + o1) = hi1; *(uint2*)(XLO + o1) = lo1;
    }
    asm volatile("bar.sync %0, 128;" :: "r"(wm + 1) : "memory");

    const uint4* wh = (const uint4*)(g_w2frag + wn * 2048) + lane * 2;
    const uint4* wl = (const uint4*)(g_w2frag + 8192 + wn * 2048) + lane * 2;

    // acc init from b2 (per nt column block)
    const int o0c = wn * 32 + (lane & 3) * 2;
    float d[2][4][4];
    #pragma unroll
    for (int nt = 0; nt < 4; nt++) {
        float c0 = __ldg(&b2[o0c + nt * 8]);
        float c1 = __ldg(&b2[o0c + nt * 8 + 1]);
        #pragma unroll
        for (int mt = 0; mt < 2; mt++) {
            d[mt][nt][0] = c0; d[mt][nt][1] = c1;
            d[mt][nt][2] = c0; d[mt][nt][3] = c1;
        }
    }

    mma_core(d, smem_u32(XHI), smem_u32(XLO), wh, wl, wm, lane);

    // epilogue: relu + dot W3; quad reduce; stash per out-group
    float w3r[8];
    #pragma unroll
    for (int nt = 0; nt < 4; nt++) {
        w3r[2 * nt]     = __ldg(&W3[o0c + nt * 8]);
        w3r[2 * nt + 1] = __ldg(&W3[o0c + nt * 8 + 1]);
    }
    #pragma unroll
    for (int mt = 0; mt < 2; mt++) {
        #pragma unroll
        for (int rh = 0; rh < 2; rh++) {
            float p = 0.f;
            #pragma unroll
            for (int nt = 0; nt < 4; nt++) {
                p = fmaf(w3r[2 * nt],     fmaxf(d[mt][nt][rh * 2],     0.f), p);
                p = fmaf(w3r[2 * nt + 1], fmaxf(d[mt][nt][rh * 2 + 1], 0.f), p);
            }
            p += __shfl_xor_sync(0xffffffffu, p, 1);
            p += __shfl_xor_sync(0xffffffffu, p, 2);
            if ((lane & 3) == 0) {
                int er = wm * 32 + mt * 16 + rh * 8 + (lane >> 2);
                part[er][wn] = p;
            }
        }
    }
    __syncthreads();

    if (tid < 64) {
        int e = eBase + tid;
        if (e < N_EDGES)
            out[e] = part[tid][0] + part[tid][1] + part[tid][2] + part[tid][3]
                     + __ldg(&b3[0]);
    }
}

// ---------------------------------------------------------------------------
extern "C" void kernel_launch(void* const* d_in, const int* in_sizes, int n_in,
                              void* d_out, int out_size)
{
    const float* h   = (const float*)d_in[0];
    const int*   src = (const int*)  d_in[1];
    const int*   dst = (const int*)  d_in[2];
    const float* W1  = (const float*)d_in[3];
    const float* b1  = (const float*)d_in[4];
    const float* W2  = (const float*)d_in[5];
    const float* b2  = (const float*)d_in[6];
    const float* W3  = (const float*)d_in[7];
    const float* b3  = (const float*)d_in[8];
    float* out = (float*)d_out;

    const int smem_sz = 32768 + 1024;

    cudaFuncSetAttribute(precompute_kernel,
                         cudaFuncAttributeMaxDynamicSharedMemorySize, smem_sz);
    cudaFuncSetAttribute(edge_kernel,
                         cudaFuncAttributeMaxDynamicSharedMemorySize, smem_sz);

    int prepBlocks = (16384 + 32768 + 255) / 256;   // 192
    int nodeBlocks = ((N_NODES + 63) / 64) * 2;     // 3126
    int edgeBlocks = (N_EDGES + 63) / 64;           // 7813

    prep_frag_kernel<<<prepBlocks, 256>>>(W1, W2);
    precompute_kernel<<<nodeBlocks, 256, smem_sz>>>(h, b1);
    edge_kernel<<<edgeBlocks, 256, smem_sz>>>(src, dst, b2, W3, b3, out);
}